// round 10
// baseline (speedup 1.0000x reference)
#include <cuda_runtime.h>
#include <cuda_fp16.h>
#include <cstdint>

// Problem constants
#define NHEAD   8
#define DK      64
#define LEN     100
#define BS      32
#define DMODEL  512
#define TEMP    20.0f
#define LN8192  9.0109133f
#define C20     (20.0f / (127.0f * 127.0f * 127.0f * 127.0f))

// Pre-split normalized projections as int8 DIGITS: q ~= q8/127 + ql8/127^2.
// Layout [b][h][128 rows][16 words] (4 int8/word). Rows 100..127 never
// written -> stay zero (static init) = free padding.
__device__ __align__(16) uint32_t g_Q8h[BS * NHEAD * 128 * 16];
__device__ __align__(16) uint32_t g_Q8l[BS * NHEAD * 128 * 16];
__device__ __align__(16) uint32_t g_K8h[BS * NHEAD * 128 * 16];
__device__ __align__(16) uint32_t g_K8l[BS * NHEAD * 128 * 16];
// V^T image per (kb,h): 64 d-rows x 60 words (fp16 pairs, m pairs 0..111,
// m>=100 zero, words 56..59 pad).
__device__ __align__(16) uint32_t g_Vhi[BS * NHEAD * 64 * 60];

// ---------------------------------------------------------------------------
__device__ __forceinline__ void mma_f16(float c[4],
    uint32_t a0, uint32_t a1, uint32_t a2, uint32_t a3,
    uint32_t b0, uint32_t b1)
{
    asm volatile(
        "mma.sync.aligned.m16n8k16.row.col.f32.f16.f16.f32 "
        "{%0,%1,%2,%3}, {%4,%5,%6,%7}, {%8,%9}, {%0,%1,%2,%3};"
        : "+f"(c[0]), "+f"(c[1]), "+f"(c[2]), "+f"(c[3])
        : "r"(a0), "r"(a1), "r"(a2), "r"(a3), "r"(b0), "r"(b1));
}

__device__ __forceinline__ void mma_s8(int c[4],
    uint32_t a0, uint32_t a1, uint32_t a2, uint32_t a3,
    uint32_t b0, uint32_t b1)
{
    asm volatile(
        "mma.sync.aligned.m16n8k32.row.col.s32.s8.s8.s32 "
        "{%0,%1,%2,%3}, {%4,%5,%6,%7}, {%8,%9}, {%0,%1,%2,%3};"
        : "+r"(c[0]), "+r"(c[1]), "+r"(c[2]), "+r"(c[3])
        : "r"(a0), "r"(a1), "r"(a2), "r"(a3), "r"(b0), "r"(b1));
}

__device__ __forceinline__ void split2h(float x0, float x1,
                                        uint32_t& hi, uint32_t& lo)
{
    __half2 h = __floats2half2_rn(x0, x1);
    float2 hf = __half22float2(h);
    __half2 l = __floats2half2_rn(x0 - hf.x, x1 - hf.y);
    hi = *(uint32_t*)&h;
    lo = *(uint32_t*)&l;
}

__device__ __forceinline__ uint32_t pack4(int a, int b, int c, int d)
{
    return (uint32_t)(a & 255) | ((uint32_t)(b & 255) << 8) |
           ((uint32_t)(c & 255) << 16) | ((uint32_t)(d & 255) << 24);
}

// ---------------------------------------------------------------------------
// Kernel 1: projection via fp16 3-term mma + fused L2-norm; int8-digit output.
// Block = (cb, b, sel). Raw-view mapping: slab row r, band cb -> chunk
// n = r*8 + cb, h = n/100, l = n%100.
// ---------------------------------------------------------------------------
#define PJ_AHI 0
#define PJ_ALO 16128
#define PJ_BHI 32256
#define PJ_BLO 41472
#define PJ_SMEM 50688

__global__ __launch_bounds__(256) void proj_kernel(
    const float* __restrict__ q, const float* __restrict__ k,
    const float* __restrict__ w_qs, const float* __restrict__ w_ks)
{
    extern __shared__ char sm[];
    uint32_t* AHI = (uint32_t*)(sm + PJ_AHI);
    uint32_t* ALO = (uint32_t*)(sm + PJ_ALO);
    uint32_t* BHI = (uint32_t*)(sm + PJ_BHI);
    uint32_t* BLO = (uint32_t*)(sm + PJ_BLO);
    float* S = (float*)sm;

    const int cb = blockIdx.x, b = blockIdx.y, sel = blockIdx.z;
    const float* x = sel ? k : q;
    const float* w = sel ? w_ks : w_qs;
    uint32_t* GH = sel ? g_K8h : g_Q8h;
    uint32_t* GL = sel ? g_K8l : g_Q8l;

    const int tid = threadIdx.x;
    const int warp = tid >> 5, lane = tid & 31;
    const int g = lane >> 2, t = lane & 3;

    float4 pa[7], pb[4];

    #pragma unroll
    for (int u = 0; u < 7; u++) {
        const int i = tid + 256 * u, r = i >> 4, c4 = i & 15;
        pa[u] = (r < LEN)
            ? *(const float4*)(x + (size_t)(b * 100 + r) * DMODEL + c4 * 4)
            : make_float4(0.f, 0.f, 0.f, 0.f);
    }
    #pragma unroll
    for (int u = 0; u < 4; u++) {
        const int i = tid + 256 * u, r = i >> 4, c4 = i & 15;
        pb[u] = *(const float4*)(w + (size_t)(cb * 64 + r) * DMODEL + c4 * 4);
    }

    float acc[7][4] = {};

    for (int c = 0; c < 8; c++) {
        __syncthreads();
        #pragma unroll
        for (int u = 0; u < 7; u++) {
            const int i = tid + 256 * u, r = i >> 4, c4 = i & 15;
            uint32_t h0, l0, h1, l1;
            split2h(pa[u].x, pa[u].y, h0, l0);
            split2h(pa[u].z, pa[u].w, h1, l1);
            AHI[r * 36 + c4 * 2] = h0; AHI[r * 36 + c4 * 2 + 1] = h1;
            ALO[r * 36 + c4 * 2] = l0; ALO[r * 36 + c4 * 2 + 1] = l1;
        }
        #pragma unroll
        for (int u = 0; u < 4; u++) {
            const int i = tid + 256 * u, r = i >> 4, c4 = i & 15;
            uint32_t h0, l0, h1, l1;
            split2h(pb[u].x, pb[u].y, h0, l0);
            split2h(pb[u].z, pb[u].w, h1, l1);
            BHI[r * 36 + c4 * 2] = h0; BHI[r * 36 + c4 * 2 + 1] = h1;
            BLO[r * 36 + c4 * 2] = l0; BLO[r * 36 + c4 * 2 + 1] = l1;
        }
        __syncthreads();
        if (c < 7) {
            const int k0 = (c + 1) * 64;
            #pragma unroll
            for (int u = 0; u < 7; u++) {
                const int i = tid + 256 * u, r = i >> 4, c4 = i & 15;
                pa[u] = (r < LEN)
                    ? *(const float4*)(x + (size_t)(b * 100 + r) * DMODEL + k0 + c4 * 4)
                    : make_float4(0.f, 0.f, 0.f, 0.f);
            }
            #pragma unroll
            for (int u = 0; u < 4; u++) {
                const int i = tid + 256 * u, r = i >> 4, c4 = i & 15;
                pb[u] = *(const float4*)(w + (size_t)(cb * 64 + r) * DMODEL + k0 + c4 * 4);
            }
        }
        #pragma unroll
        for (int ks = 0; ks < 4; ks++) {
            const int nb = (warp * 8 + g) * 36 + ks * 8 + t;
            const uint32_t bh0 = BHI[nb], bh1 = BHI[nb + 4];
            const uint32_t bl0 = BLO[nb], bl1 = BLO[nb + 4];
            #pragma unroll
            for (int i = 0; i < 7; i++) {
                const int rb = (i * 16 + g) * 36 + ks * 8 + t;
                const uint32_t ah0 = AHI[rb], ah1 = AHI[rb + 288];
                const uint32_t ah2 = AHI[rb + 4], ah3 = AHI[rb + 292];
                const uint32_t al0 = ALO[rb], al1 = ALO[rb + 288];
                const uint32_t al2 = ALO[rb + 4], al3 = ALO[rb + 292];
                mma_f16(acc[i], ah0, ah1, ah2, ah3, bh0, bh1);
                mma_f16(acc[i], ah0, ah1, ah2, ah3, bl0, bl1);
                mma_f16(acc[i], al0, al1, al2, al3, bh0, bh1);
            }
        }
    }
    __syncthreads();

    #pragma unroll
    for (int i = 0; i < 7; i++) {
        const int cc = warp * 8 + 2 * t;
        *(float2*)(S + (i * 16 + g) * 68 + cc)     = make_float2(acc[i][0], acc[i][1]);
        *(float2*)(S + (i * 16 + g + 8) * 68 + cc) = make_float2(acc[i][2], acc[i][3]);
    }
    __syncthreads();

    // normalize slab row tid (<100) = raw-view chunk n = tid*8 + cb,
    // emit int8 digits: y ~= h/127 + l/127^2  (|err| <= 0.5/127^3)
    if (tid < LEN) {
        const float* Sr = S + tid * 68;
        float ss = 0.0f;
        #pragma unroll
        for (int u = 0; u < 16; u++) {
            float4 xv = *(const float4*)(Sr + u * 4);
            ss += xv.x * xv.x + xv.y * xv.y + xv.z * xv.z + xv.w * xv.w;
        }
        const float inv = 127.0f / fmaxf(sqrtf(ss), 1e-12f);
        const int n = tid * 8 + cb;
        const int hh = n / 100, ll = n % 100;
        const uint32_t base = ((uint32_t)(b * 8 + hh) * 128 + ll) * 16;
        #pragma unroll
        for (int u = 0; u < 16; u++) {
            float4 xv = *(const float4*)(Sr + u * 4);
            const float y0 = xv.x * inv, y1 = xv.y * inv;
            const float y2 = xv.z * inv, y3 = xv.w * inv;
            const int h0 = __float2int_rn(y0), h1 = __float2int_rn(y1);
            const int h2 = __float2int_rn(y2), h3 = __float2int_rn(y3);
            const int l0 = __float2int_rn((y0 - h0) * 127.0f);
            const int l1 = __float2int_rn((y1 - h1) * 127.0f);
            const int l2 = __float2int_rn((y2 - h2) * 127.0f);
            const int l3 = __float2int_rn((y3 - h3) * 127.0f);
            GH[base + u] = pack4(h0, h1, h2, h3);
            GL[base + u] = pack4(l0, l1, l2, l3);
        }
    }
}

// ---------------------------------------------------------------------------
// Kernel 2: build V^T single-fp16 smem image in gmem. One block per (kb,h).
// ---------------------------------------------------------------------------
__global__ __launch_bounds__(256) void vimg_kernel(const float* __restrict__ v)
{
    __shared__ uint32_t sh[64 * 60];
    const int bh = blockIdx.x;
    const int kb = bh >> 3, h = bh & 7;
    const float* vp = v + (size_t)kb * 51200 + h * 6400;
    const int tid = threadIdx.x;

    for (int e = tid; e < 64 * 60; e += 256) sh[e] = 0u;
    __syncthreads();
    for (int e = tid; e < 64 * 56; e += 256) {
        const int w = e >> 6, d = e & 63;
        const int m0 = 2 * w, m1 = 2 * w + 1;
        float x0 = (m0 < LEN) ? vp[m0 * 64 + d] : 0.0f;
        float x1 = (m1 < LEN) ? vp[m1 * 64 + d] : 0.0f;
        __half2 hv = __floats2half2_rn(x0, x1);
        sh[d * 60 + w] = *(uint32_t*)&hv;
    }
    __syncthreads();
    uint4* GH = (uint4*)(g_Vhi + (size_t)bh * 3840);
    const uint4* SH = (const uint4*)sh;
    for (int e = tid; e < 960; e += 256) GH[e] = SH[e];
}

// ---------------------------------------------------------------------------
// Kernel 3: attention per (qb,kb,h), 8 warps.
//   S[128x112] = Q K^T  via int8 IMMA m16n8k32: 4 digit products, EXACT.
//     Epilogue fused per j-strip: s = (HH*127^2 + M*127 + LL)/127^4,
//     e = exp(20*relu(s) - ln8192) -> fp16 P (own smem region, no overlay).
//   O[128x64] = P V  (fp16 1-term, unchanged from round 9).
// Q/K int8 rows: 64B data + 16B pad = 80B stride (conflict-free: (20g+t)%32
// covers all 32 banks).
// ---------------------------------------------------------------------------
#define OFF_RS   0                        // 128 rows x 2 floats = 1024B
#define OFF_Q8H  1024                     // 128 x 20 words = 10240B
#define OFF_Q8L  (OFF_Q8H + 10240)        // 11264
#define OFF_K8H  (OFF_Q8L + 10240)        // 21504: 112 x 20 words = 8960B
#define OFF_K8L  (OFF_K8H + 8960)         // 30464
#define OFF_VHI  (OFF_K8L + 8960)         // 39424: 64 x 60 words = 15360B
#define OFF_P    (OFF_VHI + 15360)        // 54784: 128 x 60 words = 30720B
#define ATTN_SMEM (OFF_P + 30720)         // 85504 -> 2 CTAs/SM

__global__ __launch_bounds__(256, 2) void attn_kernel(float* __restrict__ out)
{
    extern __shared__ char sm[];
    float* RS = (float*)(sm + OFF_RS);
    uint32_t* Q8H = (uint32_t*)(sm + OFF_Q8H);
    uint32_t* Q8L = (uint32_t*)(sm + OFF_Q8L);
    uint32_t* K8H = (uint32_t*)(sm + OFF_K8H);
    uint32_t* K8L = (uint32_t*)(sm + OFF_K8L);
    uint32_t* VHI = (uint32_t*)(sm + OFF_VHI);
    uint32_t* P   = (uint32_t*)(sm + OFF_P);

    const int bx = blockIdx.x;
    const int h  = bx & 7;
    const int qb = (bx >> 3) & 31;
    const int kb = bx >> 8;
    const int tid = threadIdx.x;
    const int warp = tid >> 5, lane = tid & 31;
    const int g = lane >> 2, t = lane & 3;

    // ---- staging: pure uint4 copies (gmem rows 16w -> smem rows 20w)
    {
        const uint4* sqh = (const uint4*)(g_Q8h + (size_t)(qb * 8 + h) * 2048);
        const uint4* sql = (const uint4*)(g_Q8l + (size_t)(qb * 8 + h) * 2048);
        uint4* dqh = (uint4*)Q8H; uint4* dql = (uint4*)Q8L;
        for (int i = tid; i < 512; i += 256) {        // Q: 128 rows x 4 uint4
            const int r = i >> 2, c = i & 3;
            const int s = r * 4 + c, d = r * 5 + c;
            dqh[d] = sqh[s]; dql[d] = sql[s];
        }
        const uint4* skh = (const uint4*)(g_K8h + (size_t)(kb * 8 + h) * 2048);
        const uint4* skl = (const uint4*)(g_K8l + (size_t)(kb * 8 + h) * 2048);
        uint4* dkh = (uint4*)K8H; uint4* dkl = (uint4*)K8L;
        for (int i = tid; i < 448; i += 256) {        // K: 112 rows x 4 uint4
            const int r = i >> 2, c = i & 3;
            const int s = r * 4 + c, d = r * 5 + c;
            dkh[d] = skh[s]; dkl[d] = skl[s];
        }
        const uint4* svh = (const uint4*)(g_Vhi + (size_t)(kb * 8 + h) * 3840);
        uint4* dvh = (uint4*)VHI;
        for (int i = tid; i < 960; i += 256) dvh[i] = svh[i];
    }
    __syncthreads();

    const int wm = warp & 3, wn = warp >> 2;
    const int r0 = wm * 32;
    const int c0 = wn * 56;

    // ---- A fragments resident (int8 digits, m16k32 layout)
    uint32_t aH[2][2][4], aL[2][2][4];
    #pragma unroll
    for (int i = 0; i < 2; i++) {
        #pragma unroll
        for (int ks = 0; ks < 2; ks++) {
            const int rb = (r0 + 16 * i + g) * 20 + ks * 8 + t;
            aH[i][ks][0] = Q8H[rb];       aH[i][ks][1] = Q8H[rb + 160];
            aH[i][ks][2] = Q8H[rb + 4];   aH[i][ks][3] = Q8H[rb + 164];
            aL[i][ks][0] = Q8L[rb];       aL[i][ks][1] = Q8L[rb + 160];
            aL[i][ks][2] = Q8L[rb + 4];   aL[i][ks][3] = Q8L[rb + 164];
        }
    }

    // ---- S phase with fused per-j epilogue
    float rs[2][2] = {};
    #pragma unroll
    for (int j = 0; j < 7; j++) {
        int ahh[2][4] = {}, am[2][4] = {}, all_[2][4] = {};
        const bool dead = (wn == 1 && j == 6);   // cols 104..111 fully masked
        if (!dead) {
            #pragma unroll
            for (int ks = 0; ks < 2; ks++) {
                const int nb = (c0 + 8 * j + g) * 20 + ks * 8 + t;
                const uint32_t bh0 = K8H[nb], bh1 = K8H[nb + 4];
                const uint32_t bl0 = K8L[nb], bl1 = K8L[nb + 4];
                #pragma unroll
                for (int i = 0; i < 2; i++) {
                    mma_s8(ahh[i], aH[i][ks][0], aH[i][ks][1], aH[i][ks][2], aH[i][ks][3], bh0, bh1);
                    mma_s8(am[i],  aH[i][ks][0], aH[i][ks][1], aH[i][ks][2], aH[i][ks][3], bl0, bl1);
                    mma_s8(am[i],  aL[i][ks][0], aL[i][ks][1], aL[i][ks][2], aL[i][ks][3], bh0, bh1);
                    mma_s8(all_[i], aL[i][ks][0], aL[i][ks][1], aL[i][ks][2], aL[i][ks][3], bl0, bl1);
                }
            }
        }
        const int col = c0 + 8 * j + 2 * t;
        #pragma unroll
        for (int i = 0; i < 2; i++) {
            float e[4];
            #pragma unroll
            for (int u = 0; u < 4; u++) {
                float sf = fmaf((float)ahh[i][u], 16129.0f,
                           fmaf((float)am[i][u], 127.0f, (float)all_[i][u]));
                e[u] = __expf(fmaf(C20, fmaxf(sf, 0.0f), -LN8192));
            }
            if (dead)           { e[0] = e[1] = e[2] = e[3] = 0.f; }
            if (col >= LEN)     { e[0] = 0.f; e[2] = 0.f; }
            if (col + 1 >= LEN) { e[1] = 0.f; e[3] = 0.f; }
            __half2 h01 = __floats2half2_rn(e[0], e[1]);
            __half2 h23 = __floats2half2_rn(e[2], e[3]);
            float2 f01 = __half22float2(h01);
            float2 f23 = __half22float2(h23);
            rs[i][0] += f01.x + f01.y;
            rs[i][1] += f23.x + f23.y;
            const int w0 = (r0 + 16 * i + g) * 60 + (c0 >> 1) + j * 4 + t;
            P[w0]       = *(uint32_t*)&h01;
            P[w0 + 480] = *(uint32_t*)&h23;
        }
    }
    // rowsum reduction (width-4 k-group shuffle), 2 partials per row
    #pragma unroll
    for (int i = 0; i < 2; i++) {
        rs[i][0] += __shfl_xor_sync(0xffffffffu, rs[i][0], 1);
        rs[i][0] += __shfl_xor_sync(0xffffffffu, rs[i][0], 2);
        rs[i][1] += __shfl_xor_sync(0xffffffffu, rs[i][1], 1);
        rs[i][1] += __shfl_xor_sync(0xffffffffu, rs[i][1], 2);
        if (t == 0) {
            RS[(r0 + 16 * i + g) * 2 + wn]     = rs[i][0];
            RS[(r0 + 16 * i + g + 8) * 2 + wn] = rs[i][1];
        }
    }
    __syncthreads();

    // ---- O phase: warp rows [r0,r0+32) x dv cols [wn*32,+32), K=112, 1-term
    float o[2][4][4] = {};
    #pragma unroll
    for (int ks = 0; ks < 7; ks++) {
        uint32_t a[2][4];
        #pragma unroll
        for (int i = 0; i < 2; i++) {
            const int rb = (r0 + 16 * i + g) * 60 + ks * 8 + t;
            a[i][0] = P[rb];        a[i][1] = P[rb + 480];
            a[i][2] = P[rb + 4];    a[i][3] = P[rb + 484];
        }
        #pragma unroll
        for (int j = 0; j < 4; j++) {
            const int nb = (wn * 32 + 8 * j + g) * 60 + ks * 8 + t;
            const uint32_t bh0 = VHI[nb], bh1 = VHI[nb + 4];
            #pragma unroll
            for (int i = 0; i < 2; i++) {
                mma_f16(o[i][j], a[i][0], a[i][1], a[i][2], a[i][3], bh0, bh1);
            }
        }
    }

    // ---- output: divide by rowsum, write [kb][qb][l][h*64+d]
    const size_t ob = (size_t)(kb * 32 + qb) * LEN * DMODEL + h * 64;
    #pragma unroll
    for (int i = 0; i < 2; i++) {
        const int r = r0 + 16 * i + g;
        float inv0 = 0.f, inv1 = 0.f;
        if (r < LEN)     inv0 = 1.0f / (RS[r * 2] + RS[r * 2 + 1]);
        if (r + 8 < LEN) inv1 = 1.0f / (RS[(r + 8) * 2] + RS[(r + 8) * 2 + 1]);
        #pragma unroll
        for (int j = 0; j < 4; j++) {
            const int cc = wn * 32 + 8 * j + 2 * t;
            if (r < LEN) {
                *(float2*)(out + ob + (size_t)r * DMODEL + cc) =
                    make_float2(o[i][j][0] * inv0, o[i][j][1] * inv0);
            }
            if (r + 8 < LEN) {
                *(float2*)(out + ob + (size_t)(r + 8) * DMODEL + cc) =
                    make_float2(o[i][j][2] * inv1, o[i][j][3] * inv1);
            }
        }
    }
}

// ---------------------------------------------------------------------------
extern "C" void kernel_launch(void* const* d_in, const int* in_sizes, int n_in,
                              void* d_out, int out_size)
{
    const float* q    = (const float*)d_in[0];
    const float* k    = (const float*)d_in[1];
    const float* v    = (const float*)d_in[2];
    const float* w_qs = (const float*)d_in[3];
    const float* w_ks = (const float*)d_in[4];
    float* out = (float*)d_out;

    cudaFuncSetAttribute(proj_kernel,
                         cudaFuncAttributeMaxDynamicSharedMemorySize, PJ_SMEM);
    cudaFuncSetAttribute(attn_kernel,
                         cudaFuncAttributeMaxDynamicSharedMemorySize, ATTN_SMEM);

    proj_kernel<<<dim3(8, 32, 2), 256, PJ_SMEM>>>(q, k, w_qs, w_ks);
    vimg_kernel<<<256, 256>>>(v);
    attn_kernel<<<8192, 256, ATTN_SMEM>>>(out);
}

// round 11
// speedup vs baseline: 1.7265x; 1.7265x over previous
#include <cuda_runtime.h>
#include <cuda_fp16.h>
#include <cstdint>

// Problem constants
#define NHEAD   8
#define DK      64
#define LEN     100
#define BS      32
#define DMODEL  512
#define TEMP    20.0f
#define LN8192  9.0109133f
#define RSCALE  32.0f          // residual scale for 2-mma exact-ish S
#define RINV    0.03125f       // 1/32

// Pre-split normalized projections (fp16): Qh = fp16(q), X = fp16(Qh + 32*(q-Qh)).
// Layout [b][h][128 rows][32 words] (2 fp16/word). Rows 100..127 never
// written -> stay zero (static init) = free padding.
__device__ __align__(16) uint32_t g_Qh[BS * NHEAD * 128 * 32];
__device__ __align__(16) uint32_t g_Qx[BS * NHEAD * 128 * 32];
__device__ __align__(16) uint32_t g_Kh[BS * NHEAD * 128 * 32];
__device__ __align__(16) uint32_t g_Kx[BS * NHEAD * 128 * 32];
// V^T image per (kb,h): 64 d-rows x 60 words (fp16 pairs, m pairs 0..111,
// m>=100 zero, words 56..59 pad).
__device__ __align__(16) uint32_t g_Vhi[BS * NHEAD * 64 * 60];

// ---------------------------------------------------------------------------
__device__ __forceinline__ void mma_f16(float c[4],
    uint32_t a0, uint32_t a1, uint32_t a2, uint32_t a3,
    uint32_t b0, uint32_t b1)
{
    asm volatile(
        "mma.sync.aligned.m16n8k16.row.col.f32.f16.f16.f32 "
        "{%0,%1,%2,%3}, {%4,%5,%6,%7}, {%8,%9}, {%0,%1,%2,%3};"
        : "+f"(c[0]), "+f"(c[1]), "+f"(c[2]), "+f"(c[3])
        : "r"(a0), "r"(a1), "r"(a2), "r"(a3), "r"(b0), "r"(b1));
}

__device__ __forceinline__ void split2h(float x0, float x1,
                                        uint32_t& hi, uint32_t& lo)
{
    __half2 h = __floats2half2_rn(x0, x1);
    float2 hf = __half22float2(h);
    __half2 l = __floats2half2_rn(x0 - hf.x, x1 - hf.y);
    hi = *(uint32_t*)&h;
    lo = *(uint32_t*)&l;
}

// h = fp16(y), x = fp16(h + 32*(y-h))  (scaled-residual pair)
__device__ __forceinline__ void splitrx(float y0, float y1,
                                        uint32_t& hw, uint32_t& xw)
{
    __half2 h = __floats2half2_rn(y0, y1);
    float2 hf = __half22float2(h);
    __half2 x = __floats2half2_rn(fmaf(RSCALE, y0 - hf.x, hf.x),
                                  fmaf(RSCALE, y1 - hf.y, hf.y));
    hw = *(uint32_t*)&h;
    xw = *(uint32_t*)&x;
}

// ---------------------------------------------------------------------------
// Kernel 1: projection via fp16 3-term mma + fused L2-norm.
// Output: scaled-residual fp16 pairs (Qh, X) per element.
// Block = (cb, b, sel). Raw-view mapping: slab row r, band cb -> chunk
// n = r*8 + cb, h = n/100, l = n%100.
// ---------------------------------------------------------------------------
#define PJ_AHI 0
#define PJ_ALO 16128
#define PJ_BHI 32256
#define PJ_BLO 41472
#define PJ_SMEM 50688

__global__ __launch_bounds__(256) void proj_kernel(
    const float* __restrict__ q, const float* __restrict__ k,
    const float* __restrict__ w_qs, const float* __restrict__ w_ks)
{
    extern __shared__ char sm[];
    uint32_t* AHI = (uint32_t*)(sm + PJ_AHI);
    uint32_t* ALO = (uint32_t*)(sm + PJ_ALO);
    uint32_t* BHI = (uint32_t*)(sm + PJ_BHI);
    uint32_t* BLO = (uint32_t*)(sm + PJ_BLO);
    float* S = (float*)sm;

    const int cb = blockIdx.x, b = blockIdx.y, sel = blockIdx.z;
    const float* x = sel ? k : q;
    const float* w = sel ? w_ks : w_qs;
    uint32_t* GH = sel ? g_Kh : g_Qh;
    uint32_t* GX = sel ? g_Kx : g_Qx;

    const int tid = threadIdx.x;
    const int warp = tid >> 5, lane = tid & 31;
    const int g = lane >> 2, t = lane & 3;

    float4 pa[7], pb[4];

    #pragma unroll
    for (int u = 0; u < 7; u++) {
        const int i = tid + 256 * u, r = i >> 4, c4 = i & 15;
        pa[u] = (r < LEN)
            ? *(const float4*)(x + (size_t)(b * 100 + r) * DMODEL + c4 * 4)
            : make_float4(0.f, 0.f, 0.f, 0.f);
    }
    #pragma unroll
    for (int u = 0; u < 4; u++) {
        const int i = tid + 256 * u, r = i >> 4, c4 = i & 15;
        pb[u] = *(const float4*)(w + (size_t)(cb * 64 + r) * DMODEL + c4 * 4);
    }

    float acc[7][4] = {};

    for (int c = 0; c < 8; c++) {
        __syncthreads();
        #pragma unroll
        for (int u = 0; u < 7; u++) {
            const int i = tid + 256 * u, r = i >> 4, c4 = i & 15;
            uint32_t h0, l0, h1, l1;
            split2h(pa[u].x, pa[u].y, h0, l0);
            split2h(pa[u].z, pa[u].w, h1, l1);
            AHI[r * 36 + c4 * 2] = h0; AHI[r * 36 + c4 * 2 + 1] = h1;
            ALO[r * 36 + c4 * 2] = l0; ALO[r * 36 + c4 * 2 + 1] = l1;
        }
        #pragma unroll
        for (int u = 0; u < 4; u++) {
            const int i = tid + 256 * u, r = i >> 4, c4 = i & 15;
            uint32_t h0, l0, h1, l1;
            split2h(pb[u].x, pb[u].y, h0, l0);
            split2h(pb[u].z, pb[u].w, h1, l1);
            BHI[r * 36 + c4 * 2] = h0; BHI[r * 36 + c4 * 2 + 1] = h1;
            BLO[r * 36 + c4 * 2] = l0; BLO[r * 36 + c4 * 2 + 1] = l1;
        }
        __syncthreads();
        if (c < 7) {
            const int k0 = (c + 1) * 64;
            #pragma unroll
            for (int u = 0; u < 7; u++) {
                const int i = tid + 256 * u, r = i >> 4, c4 = i & 15;
                pa[u] = (r < LEN)
                    ? *(const float4*)(x + (size_t)(b * 100 + r) * DMODEL + k0 + c4 * 4)
                    : make_float4(0.f, 0.f, 0.f, 0.f);
            }
            #pragma unroll
            for (int u = 0; u < 4; u++) {
                const int i = tid + 256 * u, r = i >> 4, c4 = i & 15;
                pb[u] = *(const float4*)(w + (size_t)(cb * 64 + r) * DMODEL + k0 + c4 * 4);
            }
        }
        #pragma unroll
        for (int ks = 0; ks < 4; ks++) {
            const int nb = (warp * 8 + g) * 36 + ks * 8 + t;
            const uint32_t bh0 = BHI[nb], bh1 = BHI[nb + 4];
            const uint32_t bl0 = BLO[nb], bl1 = BLO[nb + 4];
            #pragma unroll
            for (int i = 0; i < 7; i++) {
                const int rb = (i * 16 + g) * 36 + ks * 8 + t;
                const uint32_t ah0 = AHI[rb], ah1 = AHI[rb + 288];
                const uint32_t ah2 = AHI[rb + 4], ah3 = AHI[rb + 292];
                const uint32_t al0 = ALO[rb], al1 = ALO[rb + 288];
                const uint32_t al2 = ALO[rb + 4], al3 = ALO[rb + 292];
                mma_f16(acc[i], ah0, ah1, ah2, ah3, bh0, bh1);
                mma_f16(acc[i], ah0, ah1, ah2, ah3, bl0, bl1);
                mma_f16(acc[i], al0, al1, al2, al3, bh0, bh1);
            }
        }
    }
    __syncthreads();

    #pragma unroll
    for (int i = 0; i < 7; i++) {
        const int cc = warp * 8 + 2 * t;
        *(float2*)(S + (i * 16 + g) * 68 + cc)     = make_float2(acc[i][0], acc[i][1]);
        *(float2*)(S + (i * 16 + g + 8) * 68 + cc) = make_float2(acc[i][2], acc[i][3]);
    }
    __syncthreads();

    // normalize slab row tid (<100) = raw-view chunk n = tid*8 + cb,
    // emit scaled-residual pair (h, x)
    if (tid < LEN) {
        const float* Sr = S + tid * 68;
        float ss = 0.0f;
        #pragma unroll
        for (int u = 0; u < 16; u++) {
            float4 xv = *(const float4*)(Sr + u * 4);
            ss += xv.x * xv.x + xv.y * xv.y + xv.z * xv.z + xv.w * xv.w;
        }
        const float inv = 1.0f / fmaxf(sqrtf(ss), 1e-12f);
        const int n = tid * 8 + cb;
        const int hh = n / 100, ll = n % 100;
        const uint32_t base = ((uint32_t)(b * 8 + hh) * 128 + ll) * 32;
        #pragma unroll
        for (int u = 0; u < 16; u++) {
            float4 xv = *(const float4*)(Sr + u * 4);
            uint32_t h0, x0, h1, x1;
            splitrx(xv.x * inv, xv.y * inv, h0, x0);
            splitrx(xv.z * inv, xv.w * inv, h1, x1);
            GH[base + u * 2] = h0; GH[base + u * 2 + 1] = h1;
            GX[base + u * 2] = x0; GX[base + u * 2 + 1] = x1;
        }
    }
}

// ---------------------------------------------------------------------------
// Kernel 2: build V^T single-fp16 smem image in gmem. One block per (kb,h).
// ---------------------------------------------------------------------------
__global__ __launch_bounds__(256) void vimg_kernel(const float* __restrict__ v)
{
    __shared__ uint32_t sh[64 * 60];
    const int bh = blockIdx.x;
    const int kb = bh >> 3, h = bh & 7;
    const float* vp = v + (size_t)kb * 51200 + h * 6400;
    const int tid = threadIdx.x;

    for (int e = tid; e < 64 * 60; e += 256) sh[e] = 0u;
    __syncthreads();
    for (int e = tid; e < 64 * 56; e += 256) {
        const int w = e >> 6, d = e & 63;
        const int m0 = 2 * w, m1 = 2 * w + 1;
        float x0 = (m0 < LEN) ? vp[m0 * 64 + d] : 0.0f;
        float x1 = (m1 < LEN) ? vp[m1 * 64 + d] : 0.0f;
        __half2 hv = __floats2half2_rn(x0, x1);
        sh[d * 60 + w] = *(uint32_t*)&hv;
    }
    __syncthreads();
    uint4* GH = (uint4*)(g_Vhi + (size_t)bh * 3840);
    const uint4* SH = (const uint4*)sh;
    for (int e = tid; e < 960; e += 256) GH[e] = SH[e];
}

// ---------------------------------------------------------------------------
// Kernel 3: attention per (qb,kb,h), 8 warps.
//   S[128x112] = Q K^T via 2-mma scaled-residual fp16:
//     s = s_hh + (s_xy - s_hh)/32   (error ~31*Ql*Kl ~ 8e-7, negligible)
//   Per-j fused epilogue: e = exp(20*relu(s) - ln8192) -> fp16 P.
//   P overlays Q smem (safe: all Q reads hoisted to reg A-cache + barrier).
//   O[128x64] = P V (fp16 1-term). Rowsums from rounded fp16 P.
// ---------------------------------------------------------------------------
#define OFF_RS   0                       // 128 rows x 2 floats = 1024B
#define OFF_QH   1024                    // 128 x 36 words = 18432B
#define OFF_QX   19456
#define OFF_KH   37888                   // 112 x 36 words = 16128B
#define OFF_KX   54016
#define OFF_VHI  70144                   // 64 x 60 words = 15360B
#define ATTN_SMEM 85504                  // -> 2 CTAs/SM
#define OFF_P    1024                    // overlays QH/QX: 128 x 60 w = 30720B

__global__ __launch_bounds__(256, 2) void attn_kernel(float* __restrict__ out)
{
    extern __shared__ char sm[];
    float* RS = (float*)(sm + OFF_RS);
    uint32_t* QH = (uint32_t*)(sm + OFF_QH);
    uint32_t* QX = (uint32_t*)(sm + OFF_QX);
    uint32_t* KH = (uint32_t*)(sm + OFF_KH);
    uint32_t* KX = (uint32_t*)(sm + OFF_KX);
    uint32_t* VHI = (uint32_t*)(sm + OFF_VHI);
    uint32_t* P   = (uint32_t*)(sm + OFF_P);

    const int bx = blockIdx.x;
    const int h  = bx & 7;
    const int qb = (bx >> 3) & 31;
    const int kb = bx >> 8;
    const int tid = threadIdx.x;
    const int warp = tid >> 5, lane = tid & 31;
    const int g = lane >> 2, t = lane & 3;

    // ---- staging: pure uint4 copies from pre-built gmem images
    {
        const uint4* sqh = (const uint4*)(g_Qh + (size_t)(qb * 8 + h) * 4096);
        const uint4* sqx = (const uint4*)(g_Qx + (size_t)(qb * 8 + h) * 4096);
        uint4* dqh = (uint4*)QH; uint4* dqx = (uint4*)QX;
        for (int i = tid; i < 1024; i += 256) {       // Q: 128 rows x 8 uint4
            const int r = i >> 3, c = i & 7;
            const int s = r * 8 + c, d = r * 9 + c;
            dqh[d] = sqh[s]; dqx[d] = sqx[s];
        }
        const uint4* skh = (const uint4*)(g_Kh + (size_t)(kb * 8 + h) * 4096);
        const uint4* skx = (const uint4*)(g_Kx + (size_t)(kb * 8 + h) * 4096);
        uint4* dkh = (uint4*)KH; uint4* dkx = (uint4*)KX;
        for (int i = tid; i < 896; i += 256) {        // K: 112 rows x 8 uint4
            const int r = i >> 3, c = i & 7;
            const int s = r * 8 + c, d = r * 9 + c;
            dkh[d] = skh[s]; dkx[d] = skx[s];
        }
        const uint4* svh = (const uint4*)(g_Vhi + (size_t)(kb * 8 + h) * 3840);
        uint4* dvh = (uint4*)VHI;
        for (int i = tid; i < 960; i += 256) dvh[i] = svh[i];
    }
    __syncthreads();

    const int wm = warp & 3, wn = warp >> 2;
    const int r0 = wm * 32;
    const int c0 = wn * 56;

    // ---- hoist ALL Q reads into register A-cache (64 regs)
    uint32_t ah[2][4][4], ax[2][4][4];
    #pragma unroll
    for (int i = 0; i < 2; i++) {
        #pragma unroll
        for (int ks = 0; ks < 4; ks++) {
            const int rb = (r0 + 16 * i + g) * 36 + ks * 8 + t;
            ah[i][ks][0] = QH[rb];       ah[i][ks][1] = QH[rb + 288];
            ah[i][ks][2] = QH[rb + 4];   ah[i][ks][3] = QH[rb + 292];
            ax[i][ks][0] = QX[rb];       ax[i][ks][1] = QX[rb + 288];
            ax[i][ks][2] = QX[rb + 4];   ax[i][ks][3] = QX[rb + 292];
        }
    }
    __syncthreads();   // Q fully consumed; P may overlay Q region

    // ---- S phase with per-j fused epilogue
    float rs[2][2] = {{0.f, 0.f}, {0.f, 0.f}};
    #pragma unroll
    for (int j = 0; j < 7; j++) {
        const bool dead = (wn == 1 && j == 6);   // cols 104..111 fully masked
        float shh[2][4] = {}, sxy[2][4] = {};
        if (!dead) {
            #pragma unroll
            for (int ks = 0; ks < 4; ks++) {
                const int nb = (c0 + 8 * j + g) * 36 + ks * 8 + t;
                const uint32_t bh0 = KH[nb], bh1 = KH[nb + 4];
                const uint32_t bx0 = KX[nb], bx1 = KX[nb + 4];
                #pragma unroll
                for (int i = 0; i < 2; i++) {
                    mma_f16(shh[i], ah[i][ks][0], ah[i][ks][1], ah[i][ks][2], ah[i][ks][3], bh0, bh1);
                    mma_f16(sxy[i], ax[i][ks][0], ax[i][ks][1], ax[i][ks][2], ax[i][ks][3], bx0, bx1);
                }
            }
        }
        const int col = c0 + 8 * j + 2 * t;
        #pragma unroll
        for (int i = 0; i < 2; i++) {
            float e[4];
            #pragma unroll
            for (int u = 0; u < 4; u++) {
                const float sf = fmaf(sxy[i][u] - shh[i][u], RINV, shh[i][u]);
                e[u] = __expf(fmaf(TEMP, fmaxf(sf, 0.0f), -LN8192));
            }
            if (dead)           { e[0] = e[1] = e[2] = e[3] = 0.f; }
            if (col >= LEN)     { e[0] = 0.f; e[2] = 0.f; }
            if (col + 1 >= LEN) { e[1] = 0.f; e[3] = 0.f; }
            __half2 h01 = __floats2half2_rn(e[0], e[1]);
            __half2 h23 = __floats2half2_rn(e[2], e[3]);
            float2 f01 = __half22float2(h01);
            float2 f23 = __half22float2(h23);
            rs[i][0] += f01.x + f01.y;
            rs[i][1] += f23.x + f23.y;
            const int w0 = (r0 + 16 * i + g) * 60 + (c0 >> 1) + j * 4 + t;
            P[w0]       = *(uint32_t*)&h01;
            P[w0 + 480] = *(uint32_t*)&h23;
        }
    }
    // rowsum reduction (width-4 k-group shuffle), 2 partials per row
    #pragma unroll
    for (int i = 0; i < 2; i++) {
        rs[i][0] += __shfl_xor_sync(0xffffffffu, rs[i][0], 1);
        rs[i][0] += __shfl_xor_sync(0xffffffffu, rs[i][0], 2);
        rs[i][1] += __shfl_xor_sync(0xffffffffu, rs[i][1], 1);
        rs[i][1] += __shfl_xor_sync(0xffffffffu, rs[i][1], 2);
        if (t == 0) {
            RS[(r0 + 16 * i + g) * 2 + wn]     = rs[i][0];
            RS[(r0 + 16 * i + g + 8) * 2 + wn] = rs[i][1];
        }
    }
    __syncthreads();

    // ---- O phase: warp rows [r0,r0+32) x dv cols [wn*32,+32), K=112, 1-term
    float o[2][4][4] = {};
    #pragma unroll
    for (int ks = 0; ks < 7; ks++) {
        uint32_t a[2][4];
        #pragma unroll
        for (int i = 0; i < 2; i++) {
            const int rb = (r0 + 16 * i + g) * 60 + ks * 8 + t;
            a[i][0] = P[rb];        a[i][1] = P[rb + 480];
            a[i][2] = P[rb + 4];    a[i][3] = P[rb + 484];
        }
        #pragma unroll
        for (int j = 0; j < 4; j++) {
            const int nb = (wn * 32 + 8 * j + g) * 60 + ks * 8 + t;
            const uint32_t bh0 = VHI[nb], bh1 = VHI[nb + 4];
            #pragma unroll
            for (int i = 0; i < 2; i++) {
                mma_f16(o[i][j], a[i][0], a[i][1], a[i][2], a[i][3], bh0, bh1);
            }
        }
    }

    // ---- output: divide by rowsum, write [kb][qb][l][h*64+d]
    const size_t ob = (size_t)(kb * 32 + qb) * LEN * DMODEL + h * 64;
    #pragma unroll
    for (int i = 0; i < 2; i++) {
        const int r = r0 + 16 * i + g;
        float inv0 = 0.f, inv1 = 0.f;
        if (r < LEN)     inv0 = 1.0f / (RS[r * 2] + RS[r * 2 + 1]);
        if (r + 8 < LEN) inv1 = 1.0f / (RS[(r + 8) * 2] + RS[(r + 8) * 2 + 1]);
        #pragma unroll
        for (int j = 0; j < 4; j++) {
            const int cc = wn * 32 + 8 * j + 2 * t;
            if (r < LEN) {
                *(float2*)(out + ob + (size_t)r * DMODEL + cc) =
                    make_float2(o[i][j][0] * inv0, o[i][j][1] * inv0);
            }
            if (r + 8 < LEN) {
                *(float2*)(out + ob + (size_t)(r + 8) * DMODEL + cc) =
                    make_float2(o[i][j][2] * inv1, o[i][j][3] * inv1);
            }
        }
    }
}

// ---------------------------------------------------------------------------
extern "C" void kernel_launch(void* const* d_in, const int* in_sizes, int n_in,
                              void* d_out, int out_size)
{
    const float* q    = (const float*)d_in[0];
    const float* k    = (const float*)d_in[1];
    const float* v    = (const float*)d_in[2];
    const float* w_qs = (const float*)d_in[3];
    const float* w_ks = (const float*)d_in[4];
    float* out = (float*)d_out;

    cudaFuncSetAttribute(proj_kernel,
                         cudaFuncAttributeMaxDynamicSharedMemorySize, PJ_SMEM);
    cudaFuncSetAttribute(attn_kernel,
                         cudaFuncAttributeMaxDynamicSharedMemorySize, ATTN_SMEM);

    proj_kernel<<<dim3(8, 32, 2), 256, PJ_SMEM>>>(q, k, w_qs, w_ks);
    vimg_kernel<<<256, 256>>>(v);
    attn_kernel<<<8192, 256, ATTN_SMEM>>>(out);
}

// round 12
// speedup vs baseline: 1.9940x; 1.1549x over previous
#include <cuda_runtime.h>
#include <cuda_fp16.h>
#include <cstdint>

// Problem constants
#define NHEAD   8
#define DK      64
#define LEN     100
#define BS      32
#define DMODEL  512
#define TEMP    20.0f
#define LN8192  9.0109133f
#define RSCALE  32.0f          // residual scale for 2-mma exact-ish S
#define RINV    0.03125f       // 1/32

// Q: FRAGMENT-ORDER image per (b,h): word idx = ((wm*2+i)*4+ks)*128 + lane*4+u
//    where u: 0=(row g,w) 1=(row g+8,w) 2=(row g,w+4) 3=(row g+8,w+4).
//    Unwritten words (rows>=100) stay zero (static init).
__device__ __align__(16) uint32_t g_Qh[BS * NHEAD * 4096];
__device__ __align__(16) uint32_t g_Qx[BS * NHEAD * 4096];
// K: row-major image per (b,h): [128 rows][32 words]. Rows 100..127 zero.
__device__ __align__(16) uint32_t g_Kh[BS * NHEAD * 4096];
__device__ __align__(16) uint32_t g_Kx[BS * NHEAD * 4096];
// V: FRAGMENT-ORDER image per (kb,h): word idx = ((jv*7)+ks)*64 + lane*2 + u,
//    u: 0 = b0 (m-pair ks*8+t), 1 = b1 (m-pair ks*8+t+4). All 3584 words written.
__device__ __align__(16) uint32_t g_Vf[BS * NHEAD * 3584];

// ---------------------------------------------------------------------------
__device__ __forceinline__ void mma_f16(float c[4],
    uint32_t a0, uint32_t a1, uint32_t a2, uint32_t a3,
    uint32_t b0, uint32_t b1)
{
    asm volatile(
        "mma.sync.aligned.m16n8k16.row.col.f32.f16.f16.f32 "
        "{%0,%1,%2,%3}, {%4,%5,%6,%7}, {%8,%9}, {%0,%1,%2,%3};"
        : "+f"(c[0]), "+f"(c[1]), "+f"(c[2]), "+f"(c[3])
        : "r"(a0), "r"(a1), "r"(a2), "r"(a3), "r"(b0), "r"(b1));
}

__device__ __forceinline__ void split2h(float x0, float x1,
                                        uint32_t& hi, uint32_t& lo)
{
    __half2 h = __floats2half2_rn(x0, x1);
    float2 hf = __half22float2(h);
    __half2 l = __floats2half2_rn(x0 - hf.x, x1 - hf.y);
    hi = *(uint32_t*)&h;
    lo = *(uint32_t*)&l;
}

// h = fp16(y), x = fp16(h + 32*(y-h))  (scaled-residual pair)
__device__ __forceinline__ void splitrx(float y0, float y1,
                                        uint32_t& hw, uint32_t& xw)
{
    __half2 h = __floats2half2_rn(y0, y1);
    float2 hf = __half22float2(h);
    __half2 x = __floats2half2_rn(fmaf(RSCALE, y0 - hf.x, hf.x),
                                  fmaf(RSCALE, y1 - hf.y, hf.y));
    hw = *(uint32_t*)&h;
    xw = *(uint32_t*)&x;
}

// ---------------------------------------------------------------------------
// Kernel 1: projection (z=0: Q frag-order out; z=1: K row-major out) +
//           z=2 slice: V^T frag-order image builder (folded vimg).
// ---------------------------------------------------------------------------
#define PJ_AHI 0
#define PJ_ALO 16128
#define PJ_BHI 32256
#define PJ_BLO 41472
#define PJ_SMEM 50688

__global__ __launch_bounds__(256) void proj_kernel(
    const float* __restrict__ q, const float* __restrict__ k,
    const float* __restrict__ w_qs, const float* __restrict__ w_ks,
    const float* __restrict__ v)
{
    const int tid = threadIdx.x;

    // ---- z == 2: V^T frag-order image, one (kb,h) per (x,y) block
    if (blockIdx.z == 2) {
        const int bh = blockIdx.y * 8 + blockIdx.x;
        const float* vp = v + (size_t)(bh >> 3) * 51200 + (bh & 7) * 6400;
        uint32_t* VF = g_Vf + (size_t)bh * 3584;
        for (int e = tid; e < 3584; e += 256) {
            const int d = e / 56, p = e % 56;          // dv col, m-pair
            const int m0 = 2 * p, m1 = 2 * p + 1;
            float x0 = (m0 < LEN) ? vp[m0 * 64 + d] : 0.0f;
            float x1 = (m1 < LEN) ? vp[m1 * 64 + d] : 0.0f;
            __half2 hv = __floats2half2_rn(x0, x1);
            const int ks = p >> 3, uh = (p >> 2) & 1, t = p & 3;
            const int jv = d >> 3, g = d & 7;
            VF[((jv * 7) + ks) * 64 + (g * 4 + t) * 2 + uh] = *(uint32_t*)&hv;
        }
        return;
    }

    extern __shared__ char sm[];
    uint32_t* AHI = (uint32_t*)(sm + PJ_AHI);
    uint32_t* ALO = (uint32_t*)(sm + PJ_ALO);
    uint32_t* BHI = (uint32_t*)(sm + PJ_BHI);
    uint32_t* BLO = (uint32_t*)(sm + PJ_BLO);
    float* S = (float*)sm;

    const int cb = blockIdx.x, b = blockIdx.y, sel = blockIdx.z;
    const float* x = sel ? k : q;
    const float* w = sel ? w_ks : w_qs;

    const int warp = tid >> 5, lane = tid & 31;
    const int g = lane >> 2, t = lane & 3;

    float4 pa[7], pb[4];

    #pragma unroll
    for (int u = 0; u < 7; u++) {
        const int i = tid + 256 * u, r = i >> 4, c4 = i & 15;
        pa[u] = (r < LEN)
            ? *(const float4*)(x + (size_t)(b * 100 + r) * DMODEL + c4 * 4)
            : make_float4(0.f, 0.f, 0.f, 0.f);
    }
    #pragma unroll
    for (int u = 0; u < 4; u++) {
        const int i = tid + 256 * u, r = i >> 4, c4 = i & 15;
        pb[u] = *(const float4*)(w + (size_t)(cb * 64 + r) * DMODEL + c4 * 4);
    }

    float acc[7][4] = {};

    for (int c = 0; c < 8; c++) {
        __syncthreads();
        #pragma unroll
        for (int u = 0; u < 7; u++) {
            const int i = tid + 256 * u, r = i >> 4, c4 = i & 15;
            uint32_t h0, l0, h1, l1;
            split2h(pa[u].x, pa[u].y, h0, l0);
            split2h(pa[u].z, pa[u].w, h1, l1);
            AHI[r * 36 + c4 * 2] = h0; AHI[r * 36 + c4 * 2 + 1] = h1;
            ALO[r * 36 + c4 * 2] = l0; ALO[r * 36 + c4 * 2 + 1] = l1;
        }
        #pragma unroll
        for (int u = 0; u < 4; u++) {
            const int i = tid + 256 * u, r = i >> 4, c4 = i & 15;
            uint32_t h0, l0, h1, l1;
            split2h(pb[u].x, pb[u].y, h0, l0);
            split2h(pb[u].z, pb[u].w, h1, l1);
            BHI[r * 36 + c4 * 2] = h0; BHI[r * 36 + c4 * 2 + 1] = h1;
            BLO[r * 36 + c4 * 2] = l0; BLO[r * 36 + c4 * 2 + 1] = l1;
        }
        __syncthreads();
        if (c < 7) {
            const int k0 = (c + 1) * 64;
            #pragma unroll
            for (int u = 0; u < 7; u++) {
                const int i = tid + 256 * u, r = i >> 4, c4 = i & 15;
                pa[u] = (r < LEN)
                    ? *(const float4*)(x + (size_t)(b * 100 + r) * DMODEL + k0 + c4 * 4)
                    : make_float4(0.f, 0.f, 0.f, 0.f);
            }
            #pragma unroll
            for (int u = 0; u < 4; u++) {
                const int i = tid + 256 * u, r = i >> 4, c4 = i & 15;
                pb[u] = *(const float4*)(w + (size_t)(cb * 64 + r) * DMODEL + k0 + c4 * 4);
            }
        }
        #pragma unroll
        for (int ks = 0; ks < 4; ks++) {
            const int nb = (warp * 8 + g) * 36 + ks * 8 + t;
            const uint32_t bh0 = BHI[nb], bh1 = BHI[nb + 4];
            const uint32_t bl0 = BLO[nb], bl1 = BLO[nb + 4];
            #pragma unroll
            for (int i = 0; i < 7; i++) {
                const int rb = (i * 16 + g) * 36 + ks * 8 + t;
                const uint32_t ah0 = AHI[rb], ah1 = AHI[rb + 288];
                const uint32_t ah2 = AHI[rb + 4], ah3 = AHI[rb + 292];
                const uint32_t al0 = ALO[rb], al1 = ALO[rb + 288];
                const uint32_t al2 = ALO[rb + 4], al3 = ALO[rb + 292];
                mma_f16(acc[i], ah0, ah1, ah2, ah3, bh0, bh1);
                mma_f16(acc[i], ah0, ah1, ah2, ah3, bl0, bl1);
                mma_f16(acc[i], al0, al1, al2, al3, bh0, bh1);
            }
        }
    }
    __syncthreads();

    #pragma unroll
    for (int i = 0; i < 7; i++) {
        const int cc = warp * 8 + 2 * t;
        *(float2*)(S + (i * 16 + g) * 68 + cc)     = make_float2(acc[i][0], acc[i][1]);
        *(float2*)(S + (i * 16 + g + 8) * 68 + cc) = make_float2(acc[i][2], acc[i][3]);
    }
    __syncthreads();

    // normalize slab row tid (<100) = raw-view chunk n = tid*8 + cb.
    if (tid < LEN) {
        const float* Sr = S + tid * 68;
        float ss = 0.0f;
        #pragma unroll
        for (int u = 0; u < 16; u++) {
            float4 xv = *(const float4*)(Sr + u * 4);
            ss += xv.x * xv.x + xv.y * xv.y + xv.z * xv.z + xv.w * xv.w;
        }
        const float inv = 1.0f / fmaxf(sqrtf(ss), 1e-12f);
        const int n = tid * 8 + cb;
        const int hh = n / 100, ll = n % 100;
        if (sel == 0) {
            // Q: scatter into FRAGMENT-ORDER image
            uint32_t* GH = g_Qh + (size_t)(b * 8 + hh) * 4096;
            uint32_t* GX = g_Qx + (size_t)(b * 8 + hh) * 4096;
            const int wm = ll >> 5, rr = ll & 31;
            const int fi = rr >> 4, gbit = (rr >> 3) & 1, gg = rr & 7;
            #pragma unroll
            for (int w = 0; w < 32; w++) {
                float2 pv = *(const float2*)(Sr + 2 * w);
                uint32_t hw, xw;
                splitrx(pv.x * inv, pv.y * inv, hw, xw);
                const int ks = w >> 3, uh = (w >> 2) & 1, tt = w & 3;
                const int idx = ((wm * 2 + fi) * 4 + ks) * 128
                              + (gg * 4 + tt) * 4 + gbit + 2 * uh;
                GH[idx] = hw; GX[idx] = xw;
            }
        } else {
            // K: row-major image
            uint32_t* GH = g_Kh + ((size_t)(b * 8 + hh) * 128 + ll) * 32;
            uint32_t* GX = g_Kx + ((size_t)(b * 8 + hh) * 128 + ll) * 32;
            #pragma unroll
            for (int u = 0; u < 16; u++) {
                float4 xv = *(const float4*)(Sr + u * 4);
                uint32_t h0, x0, h1, x1;
                splitrx(xv.x * inv, xv.y * inv, h0, x0);
                splitrx(xv.z * inv, xv.w * inv, h1, x1);
                GH[u * 2] = h0; GH[u * 2 + 1] = h1;
                GX[u * 2] = x0; GX[u * 2 + 1] = x1;
            }
        }
    }
}

// ---------------------------------------------------------------------------
// Kernel 2: attention per (qb,kb,h), 8 warps.
//   A-cache: direct LDG.128 from Q frag image (no smem, issued pre-staging).
//   S[128x112] = Q K^T via 2-mma scaled-residual fp16; per-j fused epilogue.
//   V frags: direct LDG.64 from V frag image (no smem).
//   K staged row-major -> smem (36-word stride). P in its own smem region.
// ---------------------------------------------------------------------------
#define OFF_RS   0                       // 128 rows x 2 floats = 1024B
#define OFF_KH   1024                    // 112 x 36 words = 16128B
#define OFF_KX   17152
#define OFF_P    33280                   // 128 x 60 words = 30720B
#define ATTN_SMEM 64000                  // -> 2 CTAs/SM

__global__ __launch_bounds__(256, 2) void attn_kernel(float* __restrict__ out)
{
    extern __shared__ char sm[];
    float* RS = (float*)(sm + OFF_RS);
    uint32_t* KH = (uint32_t*)(sm + OFF_KH);
    uint32_t* KX = (uint32_t*)(sm + OFF_KX);
    uint32_t* P  = (uint32_t*)(sm + OFF_P);

    const int bx = blockIdx.x;
    const int h  = bx & 7;
    const int qb = (bx >> 3) & 31;
    const int kb = bx >> 8;
    const int tid = threadIdx.x;
    const int warp = tid >> 5, lane = tid & 31;
    const int g = lane >> 2, t = lane & 3;
    const int wm = warp & 3, wn = warp >> 2;
    const int r0 = wm * 32;
    const int c0 = wn * 56;

    // ---- A-cache: direct coalesced LDG.128 from frag-order Q image (issue
    //      BEFORE K staging so the L2 latency hides behind the copy loop).
    uint32_t ah[2][4][4], ax[2][4][4];
    {
        const uint4* qh4 = (const uint4*)(g_Qh + (size_t)(qb * 8 + h) * 4096);
        const uint4* qx4 = (const uint4*)(g_Qx + (size_t)(qb * 8 + h) * 4096);
        #pragma unroll
        for (int i = 0; i < 2; i++) {
            #pragma unroll
            for (int ks = 0; ks < 4; ks++) {
                const int idx = ((wm * 2 + i) * 4 + ks) * 32 + lane;  // uint4 units
                uint4 a = qh4[idx];
                ah[i][ks][0] = a.x; ah[i][ks][1] = a.y;
                ah[i][ks][2] = a.z; ah[i][ks][3] = a.w;
                uint4 b = qx4[idx];
                ax[i][ks][0] = b.x; ax[i][ks][1] = b.y;
                ax[i][ks][2] = b.z; ax[i][ks][3] = b.w;
            }
        }
    }

    // ---- K staging: row-major gmem -> smem (stride 36 words)
    {
        const uint4* skh = (const uint4*)(g_Kh + (size_t)(kb * 8 + h) * 4096);
        const uint4* skx = (const uint4*)(g_Kx + (size_t)(kb * 8 + h) * 4096);
        uint4* dkh = (uint4*)KH; uint4* dkx = (uint4*)KX;
        for (int i = tid; i < 896; i += 256) {        // K: 112 rows x 8 uint4
            const int r = i >> 3, c = i & 7;
            const int s = r * 8 + c, d = r * 9 + c;
            dkh[d] = skh[s]; dkx[d] = skx[s];
        }
    }
    __syncthreads();

    // ---- S phase with per-j fused epilogue
    float rs[2][2] = {{0.f, 0.f}, {0.f, 0.f}};
    #pragma unroll
    for (int j = 0; j < 7; j++) {
        const bool dead = (wn == 1 && j == 6);   // cols 104..111 fully masked
        float shh[2][4] = {}, sxy[2][4] = {};
        if (!dead) {
            #pragma unroll
            for (int ks = 0; ks < 4; ks++) {
                const int nb = (c0 + 8 * j + g) * 36 + ks * 8 + t;
                const uint32_t bh0 = KH[nb], bh1 = KH[nb + 4];
                const uint32_t bx0 = KX[nb], bx1 = KX[nb + 4];
                #pragma unroll
                for (int i = 0; i < 2; i++) {
                    mma_f16(shh[i], ah[i][ks][0], ah[i][ks][1], ah[i][ks][2], ah[i][ks][3], bh0, bh1);
                    mma_f16(sxy[i], ax[i][ks][0], ax[i][ks][1], ax[i][ks][2], ax[i][ks][3], bx0, bx1);
                }
            }
        }
        const int col = c0 + 8 * j + 2 * t;
        #pragma unroll
        for (int i = 0; i < 2; i++) {
            float e[4];
            #pragma unroll
            for (int u = 0; u < 4; u++) {
                const float sf = fmaf(sxy[i][u] - shh[i][u], RINV, shh[i][u]);
                e[u] = __expf(fmaf(TEMP, fmaxf(sf, 0.0f), -LN8192));
            }
            if (dead)           { e[0] = e[1] = e[2] = e[3] = 0.f; }
            if (col >= LEN)     { e[0] = 0.f; e[2] = 0.f; }
            if (col + 1 >= LEN) { e[1] = 0.f; e[3] = 0.f; }
            rs[i][0] += e[0] + e[1];
            rs[i][1] += e[2] + e[3];
            __half2 h01 = __floats2half2_rn(e[0], e[1]);
            __half2 h23 = __floats2half2_rn(e[2], e[3]);
            const int w0 = (r0 + 16 * i + g) * 60 + (c0 >> 1) + j * 4 + t;
            P[w0]       = *(uint32_t*)&h01;
            P[w0 + 480] = *(uint32_t*)&h23;
        }
    }
    // rowsum reduction (width-4 k-group shuffle), 2 partials per row
    #pragma unroll
    for (int i = 0; i < 2; i++) {
        rs[i][0] += __shfl_xor_sync(0xffffffffu, rs[i][0], 1);
        rs[i][0] += __shfl_xor_sync(0xffffffffu, rs[i][0], 2);
        rs[i][1] += __shfl_xor_sync(0xffffffffu, rs[i][1], 1);
        rs[i][1] += __shfl_xor_sync(0xffffffffu, rs[i][1], 2);
        if (t == 0) {
            RS[(r0 + 16 * i + g) * 2 + wn]     = rs[i][0];
            RS[(r0 + 16 * i + g + 8) * 2 + wn] = rs[i][1];
        }
    }
    __syncthreads();

    // ---- O phase: warp rows [r0,r0+32) x dv cols [wn*32,+32), K=112, 1-term.
    // V b-frags direct from frag-order gmem image (coalesced LDG.64).
    const uint2* vf2 = (const uint2*)(g_Vf + (size_t)(kb * 8 + h) * 3584);
    float o[2][4][4] = {};
    #pragma unroll
    for (int ks = 0; ks < 7; ks++) {
        uint32_t a[2][4];
        #pragma unroll
        for (int i = 0; i < 2; i++) {
            const int rb = (r0 + 16 * i + g) * 60 + ks * 8 + t;
            a[i][0] = P[rb];        a[i][1] = P[rb + 480];
            a[i][2] = P[rb + 4];    a[i][3] = P[rb + 484];
        }
        #pragma unroll
        for (int j = 0; j < 4; j++) {
            const uint2 bv = vf2[((wn * 4 + j) * 7 + ks) * 32 + lane];
            #pragma unroll
            for (int i = 0; i < 2; i++) {
                mma_f16(o[i][j], a[i][0], a[i][1], a[i][2], a[i][3], bv.x, bv.y);
            }
        }
    }

    // ---- output: divide by rowsum, write [kb][qb][l][h*64+d]
    const size_t ob = (size_t)(kb * 32 + qb) * LEN * DMODEL + h * 64;
    #pragma unroll
    for (int i = 0; i < 2; i++) {
        const int r = r0 + 16 * i + g;
        float inv0 = 0.f, inv1 = 0.f;
        if (r < LEN)     inv0 = 1.0f / (RS[r * 2] + RS[r * 2 + 1]);
        if (r + 8 < LEN) inv1 = 1.0f / (RS[(r + 8) * 2] + RS[(r + 8) * 2 + 1]);
        #pragma unroll
        for (int j = 0; j < 4; j++) {
            const int cc = wn * 32 + 8 * j + 2 * t;
            if (r < LEN) {
                *(float2*)(out + ob + (size_t)r * DMODEL + cc) =
                    make_float2(o[i][j][0] * inv0, o[i][j][1] * inv0);
            }
            if (r + 8 < LEN) {
                *(float2*)(out + ob + (size_t)(r + 8) * DMODEL + cc) =
                    make_float2(o[i][j][2] * inv1, o[i][j][3] * inv1);
            }
        }
    }
}

// ---------------------------------------------------------------------------
extern "C" void kernel_launch(void* const* d_in, const int* in_sizes, int n_in,
                              void* d_out, int out_size)
{
    const float* q    = (const float*)d_in[0];
    const float* k    = (const float*)d_in[1];
    const float* v    = (const float*)d_in[2];
    const float* w_qs = (const float*)d_in[3];
    const float* w_ks = (const float*)d_in[4];
    float* out = (float*)d_out;

    cudaFuncSetAttribute(proj_kernel,
                         cudaFuncAttributeMaxDynamicSharedMemorySize, PJ_SMEM);
    cudaFuncSetAttribute(attn_kernel,
                         cudaFuncAttributeMaxDynamicSharedMemorySize, ATTN_SMEM);

    proj_kernel<<<dim3(8, 32, 3), 256, PJ_SMEM>>>(q, k, w_qs, w_ks, v);
    attn_kernel<<<8192, 256, ATTN_SMEM>>>(out);
}